// round 6
// baseline (speedup 1.0000x reference)
#include <cuda_runtime.h>
#include <cstdint>
#include <cstddef>

#define SEQ   2048
#define BATCH 64
#define DIN   512
#define HID   512
#define NBLK  128
#define NTHR  512
#define UNITS 4
#define NR    16

#define WST   1028        // W row stride in floats (257 atoms, odd -> conflict-free)
#define ABST  260         // A buffer row stride in floats (65 atoms, odd -> conflict-free)
#define PST   20          // psm row stride (floats)

// shared layout (float offsets)
#define SM_W   0
#define SM_A0  (16*WST)                 // chunk buffer 0: [64][ABST]
#define SM_A1  (SM_A0 + 64*ABST)        // chunk buffer 1
#define SM_P   (SM_A1 + 64*ABST)        // psm [4][64][PST]
#define SM_B   (SM_P + 4*64*PST)        // bias [16]
#define SM_C   (SM_B + 16)              // cell [256]
#define SM_MB  (SM_C + 256)             // 2 mbarriers (8B each)
#define SM_TOT (SM_MB + 4)
#define SMEM_BYTES (SM_TOT*4)           // 220,496 B

// ---- persistent scratch (no allocs) ----
__device__ float             g_h[2][BATCH * HID];   // ping-pong hidden state
__device__ volatile unsigned g_flags[NBLK * 64];    // one flag per block, 256B stride
__device__ unsigned          g_done;

// ---- helpers ----
__device__ __forceinline__ void fma2(unsigned long long& acc,
                                     unsigned long long a,
                                     unsigned long long b) {
    asm volatile("fma.rn.f32x2 %0, %1, %2, %0;" : "+l"(acc) : "l"(a), "l"(b));
}
__device__ __forceinline__ float2 unpk(unsigned long long v) {
    float2 f;
    asm("mov.b64 {%0, %1}, %2;" : "=f"(f.x), "=f"(f.y) : "l"(v));
    return f;
}
__device__ __forceinline__ float sigmoidf_(float x) { return 1.0f / (1.0f + __expf(-x)); }

__device__ __forceinline__ void mbar_init(uint32_t mbar, unsigned cnt) {
    asm volatile("mbarrier.init.shared.b64 [%0], %1;" :: "r"(mbar), "r"(cnt) : "memory");
}
// additive expect_tx + arrive, then the bulk copy referencing the same mbar
__device__ __forceinline__ void stage_row_1k(uint32_t dst, const float* src, uint32_t mbar) {
    asm volatile("mbarrier.arrive.expect_tx.shared::cta.b64 _, [%0], %1;"
                 :: "r"(mbar), "r"(1024u) : "memory");
    asm volatile("cp.async.bulk.shared::cluster.global.mbarrier::complete_tx::bytes "
                 "[%0], [%1], %2, [%3];"
                 :: "r"(dst), "l"(src), "r"(1024u), "r"(mbar) : "memory");
}
__device__ __forceinline__ void mbar_wait(uint32_t mbar, unsigned parity) {
    unsigned done;
    asm volatile("{\n\t.reg .pred p;\n\t"
                 "mbarrier.try_wait.parity.acquire.cta.shared::cta.b64 p, [%1], %2;\n\t"
                 "selp.b32 %0, 1, 0, p;\n\t}"
                 : "=r"(done) : "r"(mbar), "r"(parity) : "memory");
    while (!done) {
        asm volatile("{\n\t.reg .pred p;\n\t"
                     "mbarrier.try_wait.parity.acquire.cta.shared::cta.b64 p, [%1], %2;\n\t"
                     "selp.b32 %0, 1, 0, p;\n\t}"
                     : "=r"(done) : "r"(mbar), "r"(parity) : "memory");
    }
}

__global__ void __launch_bounds__(NTHR, 1)
lstm_kernel(const float* __restrict__ x,
            const float* __restrict__ Wf_, const float* __restrict__ bf_,
            const float* __restrict__ Wi_, const float* __restrict__ bi_,
            const float* __restrict__ Wg_, const float* __restrict__ bg_,
            const float* __restrict__ Wo_, const float* __restrict__ bo_,
            float* __restrict__ out)
{
    extern __shared__ float smem[];
    float* Wsm = smem + SM_W;
    float* A0  = smem + SM_A0;
    float* A1  = smem + SM_A1;
    float* psm = smem + SM_P;
    float* bsm = smem + SM_B;
    float* csm = smem + SM_C;

    const int tid = threadIdx.x;
    const int bid = blockIdx.x;
    const int j0  = bid * UNITS;

    const uint32_t a0_u32 = (uint32_t)__cvta_generic_to_shared(A0);
    const uint32_t a1_u32 = (uint32_t)__cvta_generic_to_shared(A1);
    const uint32_t mb0    = (uint32_t)__cvta_generic_to_shared(smem + SM_MB);
    const uint32_t mb1    = mb0 + 8;

    // ---- init: weights/bias to smem, h0/c0 zero, mbarriers ----
    {
        const float* Wptr[4] = { Wf_, Wi_, Wg_, Wo_ };
        for (int idx = tid; idx < 16 * 256; idx += NTHR) {   // 16 rows x 256 float4
            int rr = idx >> 8;
            int c4 = idx & 255;
            int u = rr >> 2, gg = rr & 3;
            const float4* src = (const float4*)(Wptr[gg] + (size_t)(j0 + u) * 1024);
            *(float4*)(Wsm + rr * WST + c4 * 4) = src[c4];
        }
        if (tid < NR) {
            int u = tid >> 2, gg = tid & 3;
            const float* bp = (gg == 0) ? bf_ : (gg == 1) ? bi_ : (gg == 2) ? bg_ : bo_;
            bsm[tid] = bp[j0 + u];
        }
        if (tid < 256) {
            csm[tid] = 0.0f;
            int b = tid & 63, u = tid >> 6;
            g_h[0][b * HID + j0 + u] = 0.0f;
            __threadfence();                 // writer-side release
        }
        if (tid == 0) { mbar_init(mb0, 64); mbar_init(mb1, 64); }
    }
    __syncthreads();

    const bool stager = ((tid & 7) == 0);   // 64 stagers, 4 per warp
    const int  srow   = tid >> 3;           // staged row 0..63
    const uint32_t d0 = a0_u32 + (uint32_t)srow * (ABST * 4);
    const uint32_t d1 = a1_u32 + (uint32_t)srow * (ABST * 4);

    // prologue: stage step-0 x chunks; publish h0 flag
    if (stager) {
        const float* xr = x + (size_t)srow * 512;
        stage_row_1k(d0, xr,       mb0);    // x cols [0,256)
        stage_row_1k(d1, xr + 256, mb1);    // x cols [256,512)
    }
    if (tid == 0) {
        __threadfence();
        g_flags[bid * 64] = 1u;             // "h0 slice visible"
    }

    // ---- GEMM thread decomposition (split-K by 4 within each chunk) ----
    const int g     = tid >> 7;          // K-quarter within chunk
    const int gt    = tid & 127;
    const int wb    = gt >> 5;
    const int lane  = gt & 31;
    const int rg    = lane >> 2;         // W row 0..7 (also rg+8)
    const int bg    = lane & 3;
    const int bbase = wb * 16 + bg;      // batches bbase + {0,4,8,12}

    for (int t = 0; t < SEQ; ++t) {
        const int p = t & 1;
        const float* __restrict__ hprev = g_h[p];
        const float* __restrict__ xnext = x + (size_t)(t + 1) * BATCH * DIN;

        unsigned long long a00 = 0, a01 = 0, a02 = 0, a03 = 0;
        unsigned long long a10 = 0, a11 = 0, a12 = 0, a13 = 0;

        auto compute_chunk = [&](int chunk, const float* Abuf) {
            const float* wp0 = Wsm + rg * WST + chunk * 256 + g * 64;
            const float* wp1 = wp0 + 8 * WST;
            const float* ap  = Abuf + (size_t)bbase * ABST + g * 64;
            #pragma unroll
            for (int kq = 0; kq < 16; ++kq) {
                ulonglong2 w0 = *(const ulonglong2*)(wp0 + kq * 4);
                ulonglong2 w1 = *(const ulonglong2*)(wp1 + kq * 4);
                ulonglong2 b0 = *(const ulonglong2*)(ap + 0 * 4 * ABST + kq * 4);
                ulonglong2 b1 = *(const ulonglong2*)(ap + 1 * 4 * ABST + kq * 4);
                ulonglong2 b2 = *(const ulonglong2*)(ap + 2 * 4 * ABST + kq * 4);
                ulonglong2 b3 = *(const ulonglong2*)(ap + 3 * 4 * ABST + kq * 4);
                fma2(a00, b0.x, w0.x); fma2(a00, b0.y, w0.y);
                fma2(a01, b1.x, w0.x); fma2(a01, b1.y, w0.y);
                fma2(a02, b2.x, w0.x); fma2(a02, b2.y, w0.y);
                fma2(a03, b3.x, w0.x); fma2(a03, b3.y, w0.y);
                fma2(a10, b0.x, w1.x); fma2(a10, b0.y, w1.y);
                fma2(a11, b1.x, w1.x); fma2(a11, b1.y, w1.y);
                fma2(a12, b2.x, w1.x); fma2(a12, b2.y, w1.y);
                fma2(a13, b3.x, w1.x); fma2(a13, b3.y, w1.y);
            }
        };

        // chunk 0 : x[0,256)         (staged last step / prologue, parity 0)
        mbar_wait(mb0, 0);
        compute_chunk(0, A0);
        // overlap flag propagation with the x-compute we just did
        if (tid < 128) {
            const unsigned target = (unsigned)(t + 1);
            while (g_flags[tid * 64] < target) { }
        }
        __threadfence();                   // consumer-side acquire
        __syncthreads();                   // chunk0 consumed + flags observed
        if (stager) stage_row_1k(d0, hprev + (size_t)srow * 512, mb0);       // h[0,256)

        // chunk 1 : x[256,512)
        mbar_wait(mb1, 0);
        compute_chunk(1, A1);
        __syncthreads();                   // chunk1 consumed
        if (stager) stage_row_1k(d1, hprev + (size_t)srow * 512 + 256, mb1); // h[256,512)

        // chunk 2 : h[0,256)
        mbar_wait(mb0, 1);
        compute_chunk(2, A0);
        __syncthreads();                   // chunk2 consumed
        if (stager && t + 1 < SEQ)
            stage_row_1k(d0, xnext + (size_t)srow * 512, mb0);               // next x[0,256)

        // chunk 3 : h[256,512)
        mbar_wait(mb1, 1);
        compute_chunk(3, A1);

        // ---- write partial sums ----
        {
            float2 v;
            int pb = g * 64 + bbase;
            v = unpk(a00); psm[(pb + 0)  * PST + rg]     = v.x + v.y;
            v = unpk(a01); psm[(pb + 4)  * PST + rg]     = v.x + v.y;
            v = unpk(a02); psm[(pb + 8)  * PST + rg]     = v.x + v.y;
            v = unpk(a03); psm[(pb + 12) * PST + rg]     = v.x + v.y;
            v = unpk(a10); psm[(pb + 0)  * PST + rg + 8] = v.x + v.y;
            v = unpk(a11); psm[(pb + 4)  * PST + rg + 8] = v.x + v.y;
            v = unpk(a12); psm[(pb + 8)  * PST + rg + 8] = v.x + v.y;
            v = unpk(a13); psm[(pb + 12) * PST + rg + 8] = v.x + v.y;
        }
        __syncthreads();                   // chunk3 consumed + psm visible

        if (stager && t + 1 < SEQ)
            stage_row_1k(d1, xnext + (size_t)srow * 512 + 256, mb1);         // next x[256,512)

        // ---- epilogue: gates -> (h, c); publish h ----
        if (tid < 256) {
            int b = tid & 63, u = tid >> 6;
            float pre[4];
            #pragma unroll
            for (int gg = 0; gg < 4; ++gg) {
                int r = u * 4 + gg;
                pre[gg] = bsm[r]
                        + psm[(0 * 64 + b) * PST + r]
                        + psm[(1 * 64 + b) * PST + r]
                        + psm[(2 * 64 + b) * PST + r]
                        + psm[(3 * 64 + b) * PST + r];
            }
            float fg  = sigmoidf_(pre[0]);
            float ig  = sigmoidf_(pre[1]);
            float gg2 = tanhf(pre[2]);
            float og  = sigmoidf_(pre[3]);
            float c   = fg * csm[tid] + ig * gg2;
            csm[tid]  = c;
            float h   = og * tanhf(c);
            g_h[p ^ 1][b * HID + j0 + u] = h;
            out[((size_t)t * BATCH + b) * HID + j0 + u] = h;
            if (t == SEQ - 1) {
                size_t base = (size_t)SEQ * BATCH * HID;
                out[base + (size_t)b * HID + j0 + u] = h;
                out[base + (size_t)BATCH * HID + (size_t)b * HID + j0 + u] = c;
            }
            __threadfence();               // writer-side release
        }
        __syncthreads();
        if (tid == 0) {
            __threadfence();               // signaler-side release
            g_flags[bid * 64] = (unsigned)(t + 2);
        }
    }

    // ---- reset persistent state for the next graph replay ----
    __syncthreads();
    if (tid == 0) {
        __threadfence();
        if (atomicAdd(&g_done, 1u) == NBLK - 1) {
            g_done = 0u;
            for (int i = 0; i < NBLK; ++i) g_flags[i * 64] = 0u;
            __threadfence();
        }
    }
}

extern "C" void kernel_launch(void* const* d_in, const int* in_sizes, int n_in,
                              void* d_out, int out_size)
{
    const float* x  = (const float*)d_in[0];
    const float* Wf = (const float*)d_in[1];
    const float* bf = (const float*)d_in[2];
    const float* Wi = (const float*)d_in[3];
    const float* bi = (const float*)d_in[4];
    const float* Wg = (const float*)d_in[5];
    const float* bg = (const float*)d_in[6];
    const float* Wo = (const float*)d_in[7];
    const float* bo = (const float*)d_in[8];
    float* out = (float*)d_out;

    cudaFuncSetAttribute(lstm_kernel,
                         cudaFuncAttributeMaxDynamicSharedMemorySize, SMEM_BYTES);
    lstm_kernel<<<NBLK, NTHR, SMEM_BYTES>>>(x, Wf, bf, Wi, bi, Wg, bg, Wo, bo, out);
}

// round 7
// speedup vs baseline: 1.8332x; 1.8332x over previous
#include <cuda_runtime.h>
#include <cstdint>
#include <cstddef>

#define SEQ   2048
#define BATCH 64
#define DIN   512
#define HID   512
#define NBLK  128
#define NTHR  512
#define UNITS 4
#define NR    16

#define WST   1028        // W row stride in floats (257 atoms, odd -> conflict-free)
#define ABST  260         // A buffer row stride in floats (65 atoms, odd -> conflict-free)
#define PST   20          // psm row stride (floats)

// shared layout (float offsets)
#define SM_W   0
#define SM_A0  (16*WST)                 // chunk buffer 0: [64][ABST]
#define SM_A1  (SM_A0 + 64*ABST)        // chunk buffer 1
#define SM_P   (SM_A1 + 64*ABST)        // psm [4][64][PST]
#define SM_B   (SM_P + 4*64*PST)        // bias [16]
#define SM_C   (SM_B + 16)              // cell [256]
#define SM_MB  (SM_C + 256)             // 2 mbarriers (8B each)
#define SM_TOT (SM_MB + 4)
#define SMEM_BYTES (SM_TOT*4)           // 220,496 B

// ---- persistent scratch (no allocs) ----
__device__ float             g_h[2][BATCH * HID];   // ping-pong hidden state
__device__ volatile unsigned g_flags[NBLK * 64];    // one flag per block, 256B stride
__device__ unsigned          g_done;

// ---- helpers ----
__device__ __forceinline__ void fma2(unsigned long long& acc,
                                     unsigned long long a,
                                     unsigned long long b) {
    asm volatile("fma.rn.f32x2 %0, %1, %2, %0;" : "+l"(acc) : "l"(a), "l"(b));
}
__device__ __forceinline__ float2 unpk(unsigned long long v) {
    float2 f;
    asm("mov.b64 {%0, %1}, %2;" : "=f"(f.x), "=f"(f.y) : "l"(v));
    return f;
}
__device__ __forceinline__ float sigmoidf_(float x) { return 1.0f / (1.0f + __expf(-x)); }

__device__ __forceinline__ void mbar_init(uint32_t mbar, unsigned cnt) {
    asm volatile("mbarrier.init.shared.b64 [%0], %1;" :: "r"(mbar), "r"(cnt) : "memory");
}
// additive expect_tx + arrive, then the bulk copy referencing the same mbar
__device__ __forceinline__ void stage_row_1k(uint32_t dst, const float* src, uint32_t mbar) {
    asm volatile("mbarrier.arrive.expect_tx.shared::cta.b64 _, [%0], %1;"
                 :: "r"(mbar), "r"(1024u) : "memory");
    asm volatile("cp.async.bulk.shared::cluster.global.mbarrier::complete_tx::bytes "
                 "[%0], [%1], %2, [%3];"
                 :: "r"(dst), "l"(src), "r"(1024u), "r"(mbar) : "memory");
}
__device__ __forceinline__ void mbar_wait(uint32_t mbar, unsigned parity) {
    unsigned done;
    asm volatile("{\n\t.reg .pred p;\n\t"
                 "mbarrier.try_wait.parity.acquire.cta.shared::cta.b64 p, [%1], %2;\n\t"
                 "selp.b32 %0, 1, 0, p;\n\t}"
                 : "=r"(done) : "r"(mbar), "r"(parity) : "memory");
    while (!done) {
        asm volatile("{\n\t.reg .pred p;\n\t"
                     "mbarrier.try_wait.parity.acquire.cta.shared::cta.b64 p, [%1], %2;\n\t"
                     "selp.b32 %0, 1, 0, p;\n\t}"
                     : "=r"(done) : "r"(mbar), "r"(parity) : "memory");
    }
}

__global__ void __launch_bounds__(NTHR, 1)
lstm_kernel(const float* __restrict__ x,
            const float* __restrict__ Wf_, const float* __restrict__ bf_,
            const float* __restrict__ Wi_, const float* __restrict__ bi_,
            const float* __restrict__ Wg_, const float* __restrict__ bg_,
            const float* __restrict__ Wo_, const float* __restrict__ bo_,
            float* __restrict__ out)
{
    extern __shared__ float smem[];
    float* Wsm = smem + SM_W;
    float* A0  = smem + SM_A0;
    float* A1  = smem + SM_A1;
    float* psm = smem + SM_P;
    float* bsm = smem + SM_B;
    float* csm = smem + SM_C;

    const int tid = threadIdx.x;
    const int bid = blockIdx.x;
    const int j0  = bid * UNITS;

    const uint32_t a0_u32 = (uint32_t)__cvta_generic_to_shared(A0);
    const uint32_t a1_u32 = (uint32_t)__cvta_generic_to_shared(A1);
    const uint32_t mb0    = (uint32_t)__cvta_generic_to_shared(smem + SM_MB);
    const uint32_t mb1    = mb0 + 8;

    // ---- init: weights/bias to smem, h0/c0 zero, mbarriers ----
    {
        const float* Wptr[4] = { Wf_, Wi_, Wg_, Wo_ };
        for (int idx = tid; idx < 16 * 256; idx += NTHR) {   // 16 rows x 256 float4
            int rr = idx >> 8;
            int c4 = idx & 255;
            int u = rr >> 2, gg = rr & 3;
            const float4* src = (const float4*)(Wptr[gg] + (size_t)(j0 + u) * 1024);
            *(float4*)(Wsm + rr * WST + c4 * 4) = src[c4];
        }
        if (tid < NR) {
            int u = tid >> 2, gg = tid & 3;
            const float* bp = (gg == 0) ? bf_ : (gg == 1) ? bi_ : (gg == 2) ? bg_ : bo_;
            bsm[tid] = bp[j0 + u];
        }
        if (tid < 256) {
            csm[tid] = 0.0f;
            int b = tid & 63, u = tid >> 6;
            g_h[0][b * HID + j0 + u] = 0.0f;
            __threadfence();                 // writer-side release
        }
        if (tid == 0) { mbar_init(mb0, 64); mbar_init(mb1, 64); }
    }
    __syncthreads();

    const bool stager = ((tid & 7) == 0);   // 64 stagers, 4 per warp
    const int  srow   = tid >> 3;           // staged row 0..63
    const uint32_t d0 = a0_u32 + (uint32_t)srow * (ABST * 4);
    const uint32_t d1 = a1_u32 + (uint32_t)srow * (ABST * 4);

    // prologue: stage step-0 x chunks; publish h0 flag
    if (stager) {
        const float* xr = x + (size_t)srow * 512;
        stage_row_1k(d0, xr,       mb0);    // x cols [0,256)
        stage_row_1k(d1, xr + 256, mb1);    // x cols [256,512)
    }
    if (tid == 0) {
        __threadfence();
        g_flags[bid * 64] = 1u;             // "h0 slice visible"
    }

    // ---- GEMM thread decomposition (split-K by 4 within each chunk) ----
    const int g     = tid >> 7;          // K-quarter within chunk
    const int gt    = tid & 127;
    const int wb    = gt >> 5;
    const int lane  = gt & 31;
    const int rg    = lane >> 2;         // W row 0..7 (also rg+8)
    const int bg    = lane & 3;
    const int bbase = wb * 16 + bg;      // batches bbase + {0,4,8,12}

    for (int t = 0; t < SEQ; ++t) {
        const int p = t & 1;
        const float* __restrict__ hprev = g_h[p];
        const float* __restrict__ xnext = x + (size_t)(t + 1) * BATCH * DIN;

        unsigned long long a00 = 0, a01 = 0, a02 = 0, a03 = 0;
        unsigned long long a10 = 0, a11 = 0, a12 = 0, a13 = 0;

        auto compute_chunk = [&](int chunk, const float* Abuf) {
            const float* wp0 = Wsm + rg * WST + chunk * 256 + g * 64;
            const float* wp1 = wp0 + 8 * WST;
            const float* ap  = Abuf + (size_t)bbase * ABST + g * 64;
            #pragma unroll
            for (int kq = 0; kq < 16; ++kq) {
                ulonglong2 w0 = *(const ulonglong2*)(wp0 + kq * 4);
                ulonglong2 w1 = *(const ulonglong2*)(wp1 + kq * 4);
                ulonglong2 b0 = *(const ulonglong2*)(ap + 0 * 4 * ABST + kq * 4);
                ulonglong2 b1 = *(const ulonglong2*)(ap + 1 * 4 * ABST + kq * 4);
                ulonglong2 b2 = *(const ulonglong2*)(ap + 2 * 4 * ABST + kq * 4);
                ulonglong2 b3 = *(const ulonglong2*)(ap + 3 * 4 * ABST + kq * 4);
                fma2(a00, b0.x, w0.x); fma2(a00, b0.y, w0.y);
                fma2(a01, b1.x, w0.x); fma2(a01, b1.y, w0.y);
                fma2(a02, b2.x, w0.x); fma2(a02, b2.y, w0.y);
                fma2(a03, b3.x, w0.x); fma2(a03, b3.y, w0.y);
                fma2(a10, b0.x, w1.x); fma2(a10, b0.y, w1.y);
                fma2(a11, b1.x, w1.x); fma2(a11, b1.y, w1.y);
                fma2(a12, b2.x, w1.x); fma2(a12, b2.y, w1.y);
                fma2(a13, b3.x, w1.x); fma2(a13, b3.y, w1.y);
            }
        };

        // chunk 0 : x[0,256)         (staged last step / prologue, parity 0)
        mbar_wait(mb0, 0);
        compute_chunk(0, A0);
        // overlap flag propagation with the x-compute we just did
        if (tid < 128) {
            const unsigned target = (unsigned)(t + 1);
            while (g_flags[tid * 64] < target) { }
        }
        __threadfence();                   // consumer-side acquire
        __syncthreads();                   // chunk0 consumed + flags observed
        if (stager) stage_row_1k(d0, hprev + (size_t)srow * 512, mb0);       // h[0,256)

        // chunk 1 : x[256,512)
        mbar_wait(mb1, 0);
        compute_chunk(1, A1);
        __syncthreads();                   // chunk1 consumed
        if (stager) stage_row_1k(d1, hprev + (size_t)srow * 512 + 256, mb1); // h[256,512)

        // chunk 2 : h[0,256)
        mbar_wait(mb0, 1);
        compute_chunk(2, A0);
        __syncthreads();                   // chunk2 consumed
        if (stager && t + 1 < SEQ)
            stage_row_1k(d0, xnext + (size_t)srow * 512, mb0);               // next x[0,256)

        // chunk 3 : h[256,512)
        mbar_wait(mb1, 1);
        compute_chunk(3, A1);

        // ---- write partial sums ----
        {
            float2 v;
            int pb = g * 64 + bbase;
            v = unpk(a00); psm[(pb + 0)  * PST + rg]     = v.x + v.y;
            v = unpk(a01); psm[(pb + 4)  * PST + rg]     = v.x + v.y;
            v = unpk(a02); psm[(pb + 8)  * PST + rg]     = v.x + v.y;
            v = unpk(a03); psm[(pb + 12) * PST + rg]     = v.x + v.y;
            v = unpk(a10); psm[(pb + 0)  * PST + rg + 8] = v.x + v.y;
            v = unpk(a11); psm[(pb + 4)  * PST + rg + 8] = v.x + v.y;
            v = unpk(a12); psm[(pb + 8)  * PST + rg + 8] = v.x + v.y;
            v = unpk(a13); psm[(pb + 12) * PST + rg + 8] = v.x + v.y;
        }
        __syncthreads();                   // chunk3 consumed + psm visible

        if (stager && t + 1 < SEQ)
            stage_row_1k(d1, xnext + (size_t)srow * 512 + 256, mb1);         // next x[256,512)

        // ---- epilogue: gates -> (h, c); publish h ----
        if (tid < 256) {
            int b = tid & 63, u = tid >> 6;
            float pre[4];
            #pragma unroll
            for (int gg = 0; gg < 4; ++gg) {
                int r = u * 4 + gg;
                pre[gg] = bsm[r]
                        + psm[(0 * 64 + b) * PST + r]
                        + psm[(1 * 64 + b) * PST + r]
                        + psm[(2 * 64 + b) * PST + r]
                        + psm[(3 * 64 + b) * PST + r];
            }
            float fg  = sigmoidf_(pre[0]);
            float ig  = sigmoidf_(pre[1]);
            float gg2 = tanhf(pre[2]);
            float og  = sigmoidf_(pre[3]);
            float c   = fg * csm[tid] + ig * gg2;
            csm[tid]  = c;
            float h   = og * tanhf(c);
            g_h[p ^ 1][b * HID + j0 + u] = h;
            out[((size_t)t * BATCH + b) * HID + j0 + u] = h;
            if (t == SEQ - 1) {
                size_t base = (size_t)SEQ * BATCH * HID;
                out[base + (size_t)b * HID + j0 + u] = h;
                out[base + (size_t)BATCH * HID + (size_t)b * HID + j0 + u] = c;
            }
            __threadfence();               // writer-side release
        }
        __syncthreads();
        if (tid == 0) {
            __threadfence();               // signaler-side release
            g_flags[bid * 64] = (unsigned)(t + 2);
        }
    }

    // ---- reset persistent state for the next graph replay ----
    __syncthreads();
    if (tid == 0) {
        __threadfence();
        if (atomicAdd(&g_done, 1u) == NBLK - 1) {
            g_done = 0u;
            for (int i = 0; i < NBLK; ++i) g_flags[i * 64] = 0u;
            __threadfence();
        }
    }
}

extern "C" void kernel_launch(void* const* d_in, const int* in_sizes, int n_in,
                              void* d_out, int out_size)
{
    const float* x  = (const float*)d_in[0];
    const float* Wf = (const float*)d_in[1];
    const float* bf = (const float*)d_in[2];
    const float* Wi = (const float*)d_in[3];
    const float* bi = (const float*)d_in[4];
    const float* Wg = (const float*)d_in[5];
    const float* bg = (const float*)d_in[6];
    const float* Wo = (const float*)d_in[7];
    const float* bo = (const float*)d_in[8];
    float* out = (float*)d_out;

    cudaFuncSetAttribute(lstm_kernel,
                         cudaFuncAttributeMaxDynamicSharedMemorySize, SMEM_BYTES);
    lstm_kernel<<<NBLK, NTHR, SMEM_BYTES>>>(x, Wf, bf, Wi, bi, Wg, bg, Wo, bo, out);
}